// round 16
// baseline (speedup 1.0000x reference)
#include <cuda_runtime.h>
#include <cuda_fp16.h>
#include <cstdint>
#include <math.h>

#define CIN   64
#define COUT  128
#define HH    224
#define WW    224
#define OH    222
#define OW    222

#define TPX    16          // output px per tile (x)
#define TROWS  8           // output rows per tile (y)
#define INROWS 10          // staged input rows = TROWS + 2
#define PXST   18          // staged px per row = TPX + 2
#define SLAB_STRIDE 3072   // bytes per input row slab

// ---------------- global scratch ----------------
// a-fragment-shuffled fp16 weights: [tap(9)][ks(4)][mblk(8)][lane(32)] x uint4
__device__ uint4 g_Wfrag[9 * 4 * 8 * 32];

__global__ void prep_w(const float* __restrict__ w) {
    int i = blockIdx.x * 256 + threadIdx.x;
    if (i >= 9216) return;
    int lane = i & 31;
    int mblk = (i >> 5) & 7;
    int q    = i >> 8;            // tap*4 + ks
    int ks   = q & 3;
    int tap  = q >> 2;
    int kh = tap / 3, kw = tap - kh * 3;

    int r  = lane >> 2;
    int k0 = ks * 16 + (lane & 3) * 2;

    uint32_t words[4];
#pragma unroll
    for (int wi = 0; wi < 4; wi++) {
        int co = mblk * 16 + r + (wi & 1) * 8;
        int kk = k0 + (wi >> 1) * 8;
        uint32_t packed = 0;
#pragma unroll
        for (int j = 0; j < 2; j++) {
            float v = w[((co * CIN + (kk + j)) * 3 + kh) * 3 + kw];
            packed |= (uint32_t)__half_as_ushort(__float2half(v)) << (16 * j);
        }
        words[wi] = packed;
    }
    g_Wfrag[i] = make_uint4(words[0], words[1], words[2], words[3]);
}

// ---------------- helpers ----------------
__device__ __forceinline__ uint32_t smem_u32(const void* p) {
    uint32_t a;
    asm("{ .reg .u64 t; cvta.to.shared.u64 t, %1; cvt.u32.u64 %0, t; }" : "=r"(a) : "l"(p));
    return a;
}
__device__ __forceinline__ void ldsm4(uint32_t& r0, uint32_t& r1, uint32_t& r2, uint32_t& r3, uint32_t addr) {
    asm volatile("ldmatrix.sync.aligned.m8n8.x4.shared.b16 {%0, %1, %2, %3}, [%4];"
        : "=r"(r0), "=r"(r1), "=r"(r2), "=r"(r3) : "r"(addr));
}
__device__ __forceinline__ void mma16816(float* d, const uint4& a, uint32_t b0, uint32_t b1) {
    asm volatile("mma.sync.aligned.m16n8k16.row.col.f32.f16.f16.f32 "
        "{%0, %1, %2, %3}, {%4, %5, %6, %7}, {%8, %9}, {%0, %1, %2, %3};"
        : "+f"(d[0]), "+f"(d[1]), "+f"(d[2]), "+f"(d[3])
        : "r"(a.x), "r"(a.y), "r"(a.z), "r"(a.w), "r"(b0), "r"(b1));
}
__device__ __forceinline__ uint32_t swz(uint32_t off) { return off ^ ((off >> 3) & 0x70); }

#define OFF_MIN (INROWS * SLAB_STRIDE)            // 30720
#define SMEM_BYTES (OFF_MIN + 1024 + 1024)        // 32768

__global__ __launch_bounds__(256, 2)
void conv_mma_kernel(const float* __restrict__ x,
                     const float* __restrict__ bias,
                     float* __restrict__ out) {
    extern __shared__ char smem_raw[];
    uint32_t sb = (smem_u32(smem_raw) + 1023u) & ~1023u;

    const int tid  = threadIdx.x;
    const int wid  = tid >> 5;
    const int lane = tid & 31;
    const int b    = blockIdx.z;
    const int oy0  = blockIdx.y * TROWS;
    const int x0   = blockIdx.x * TPX;

    const int warpM = wid & 1;       // co half: 64*warpM .. +63
    const int warpN = wid >> 1;      // output row pair: rows 2*warpN, 2*warpN+1

    // ---- direct staging: fp32 x -> fp16 swizzled slabs, in-kernel ----
    // element e = (row, ci, px), px fastest (72B contiguous fp32 runs per (row,ci)).
    // 10 rows * 64 ci * 18 px = 11520 = 45 * 256 exactly.
    const float* xb = x + (size_t)b * CIN * HH * WW;
    for (int i = 0; i < 45; i++) {
        int e   = i * 256 + tid;
        int row = e / 1152;
        int v   = e - row * 1152;
        int ci  = v / 18;
        int px  = v - ci * 18;
        int y   = oy0 + row;
        int ix  = x0 + px;
        float f = (y < HH && ix < WW) ? __ldg(&xb[((size_t)ci * HH + y) * WW + ix]) : 0.0f;
        __half h = __float2half(f);
        uint32_t dst = sb + (uint32_t)(row * SLAB_STRIDE)
                     + (uint32_t)(px * 128 + (((ci >> 3) ^ (px & 7)) << 4) + (ci & 7) * 2);
        asm volatile("st.shared.u16 [%0], %1;" :: "r"(dst), "h"(__half_as_ushort(h)));
    }

    // ---- accumulators, init = bias[co] ----
    float acc[4][4][4];
#pragma unroll
    for (int m = 0; m < 4; m++) {
        int r_co = warpM * 64 + m * 16 + (lane >> 2);
        float b0 = __ldg(&bias[r_co]);
        float b1 = __ldg(&bias[r_co + 8]);
#pragma unroll
        for (int f = 0; f < 4; f++) {
            acc[m][f][0] = b0; acc[m][f][1] = b0;
            acc[m][f][2] = b1; acc[m][f][3] = b1;
        }
    }
    __syncthreads();

    const uint4* gw = g_Wfrag;
    const int pxl     = lane & 7;
    const int fhalf   = (lane >> 4) & 1;
    const int kb_lane = ((lane >> 3) & 1) * 16;
    const int awoff   = warpM * 4;

#pragma unroll
    for (int kh = 0; kh < 3; kh++) {
        const uint32_t row0 = sb + (uint32_t)((2 * warpN + kh) * SLAB_STRIDE);
#pragma unroll
        for (int kw = 0; kw < 3; kw++) {
            const int tap = kh * 3 + kw;
#pragma unroll
            for (int ks = 0; ks < 4; ks++) {
                uint4 A[4];
                const int base = (tap * 4 + ks) * 8;
#pragma unroll
                for (int m = 0; m < 4; m++)
                    A[m] = __ldg(&gw[(base + awoff + m) * 32 + lane]);

                uint32_t B[8];
#pragma unroll
                for (int h = 0; h < 2; h++) {
                    uint32_t off = swz((uint32_t)((pxl + fhalf * 8 + kw) * 128 + kb_lane + ks * 32));
                    ldsm4(B[h*4+0], B[h*4+1], B[h*4+2], B[h*4+3],
                          row0 + (uint32_t)(h * SLAB_STRIDE) + off);
                }
#pragma unroll
                for (int m = 0; m < 4; m++) {
#pragma unroll
                    for (int f = 0; f < 4; f++)
                        mma16816(acc[m][f], A[m], B[f*2], B[f*2+1]);
                }
            }
        }
    }

    // ---- epilogue: min over co ----
    float* sMin = (float*)(smem_raw + (sb - smem_u32(smem_raw)) + OFF_MIN);  // [2][128]

#pragma unroll
    for (int f = 0; f < 4; f++) {
        float v0 = __int_as_float(0x7f800000), v1 = v0;
#pragma unroll
        for (int m = 0; m < 4; m++) {
            v0 = fminf(v0, fminf(acc[m][f][0], acc[m][f][2]));
            v1 = fminf(v1, fminf(acc[m][f][1], acc[m][f][3]));
        }
#pragma unroll
        for (int off = 4; off < 32; off <<= 1) {
            v0 = fminf(v0, __shfl_xor_sync(0xffffffffu, v0, off));
            v1 = fminf(v1, __shfl_xor_sync(0xffffffffu, v1, off));
        }
        if ((lane >> 2) == 0) {
            int r_loc = 2 * warpN + (f >> 1);
            int px    = (f & 1) * 8 + (lane & 3) * 2;
            int idx   = r_loc * TPX + px;
            sMin[warpM * 128 + idx]     = v0;
            sMin[warpM * 128 + idx + 1] = v1;
        }
    }
    __syncthreads();

    if (tid < 128) {
        int r = tid >> 4, c = tid & 15;
        int orow = oy0 + r, ocol = x0 + c;
        if (orow < OH && ocol < OW) {
            float m = fminf(sMin[tid], sMin[128 + tid]);
            out[((size_t)b * OH + orow) * OW + ocol] = tanhf(tanhf(m));
        }
    }
}

extern "C" void kernel_launch(void* const* d_in, const int* in_sizes, int n_in,
                              void* d_out, int out_size) {
    const float* x    = (const float*)d_in[0];
    const float* w    = (const float*)d_in[1];
    const float* bias = (const float*)d_in[2];
    float* out = (float*)d_out;

    prep_w<<<(9216 + 255) / 256, 256>>>(w);

    cudaFuncSetAttribute(conv_mma_kernel, cudaFuncAttributeMaxDynamicSharedMemorySize, SMEM_BYTES);
    dim3 grid((OW + TPX - 1) / TPX,      // 14
              (OH + TROWS - 1) / TROWS,  // 28
              16);
    conv_mma_kernel<<<grid, 256, SMEM_BYTES>>>(x, bias, out);
}

// round 17
// speedup vs baseline: 1.5038x; 1.5038x over previous
#include <cuda_runtime.h>
#include <cuda_fp16.h>
#include <cstdint>
#include <math.h>

#define CIN   64
#define COUT  128
#define HH    224
#define WW    224
#define OH    222
#define OW    222

#define TPX    16          // output px per tile (x)
#define TROWS  8           // output rows per tile (y)
#define INROWS 10          // staged input rows = TROWS + 2
#define PXST   18          // staged px per row = TPX + 2
#define SLAB_STRIDE 3072   // bytes per fp16 input row slab

// ---------------- global scratch ----------------
// a-fragment-shuffled fp16 weights: [tap(9)][ks(4)][mblk(8)][lane(32)] x uint4
__device__ uint4 g_Wfrag[9 * 4 * 8 * 32];

__global__ void prep_w(const float* __restrict__ w) {
    int i = blockIdx.x * 256 + threadIdx.x;
    if (i >= 9216) return;
    int lane = i & 31;
    int mblk = (i >> 5) & 7;
    int q    = i >> 8;            // tap*4 + ks
    int ks   = q & 3;
    int tap  = q >> 2;
    int kh = tap / 3, kw = tap - kh * 3;

    int r  = lane >> 2;
    int k0 = ks * 16 + (lane & 3) * 2;

    uint32_t words[4];
#pragma unroll
    for (int wi = 0; wi < 4; wi++) {
        int co = mblk * 16 + r + (wi & 1) * 8;
        int kk = k0 + (wi >> 1) * 8;
        uint32_t packed = 0;
#pragma unroll
        for (int j = 0; j < 2; j++) {
            float v = w[((co * CIN + (kk + j)) * 3 + kh) * 3 + kw];
            packed |= (uint32_t)__half_as_ushort(__float2half(v)) << (16 * j);
        }
        words[wi] = packed;
    }
    g_Wfrag[i] = make_uint4(words[0], words[1], words[2], words[3]);
}

// ---------------- helpers ----------------
__device__ __forceinline__ uint32_t smem_u32(const void* p) {
    uint32_t a;
    asm("{ .reg .u64 t; cvta.to.shared.u64 t, %1; cvt.u32.u64 %0, t; }" : "=r"(a) : "l"(p));
    return a;
}
__device__ __forceinline__ void ldsm4(uint32_t& r0, uint32_t& r1, uint32_t& r2, uint32_t& r3, uint32_t addr) {
    asm volatile("ldmatrix.sync.aligned.m8n8.x4.shared.b16 {%0, %1, %2, %3}, [%4];"
        : "=r"(r0), "=r"(r1), "=r"(r2), "=r"(r3) : "r"(addr));
}
__device__ __forceinline__ void mma16816(float* d, const uint4& a, uint32_t b0, uint32_t b1) {
    asm volatile("mma.sync.aligned.m16n8k16.row.col.f32.f16.f16.f32 "
        "{%0, %1, %2, %3}, {%4, %5, %6, %7}, {%8, %9}, {%0, %1, %2, %3};"
        : "+f"(d[0]), "+f"(d[1]), "+f"(d[2]), "+f"(d[3])
        : "r"(a.x), "r"(a.y), "r"(a.z), "r"(a.w), "r"(b0), "r"(b1));
}
__device__ __forceinline__ void cp16(uint32_t dst, const void* src, int sz) {
    asm volatile("cp.async.cg.shared.global [%0], [%1], 16, %2;"
        :: "r"(dst), "l"(src), "r"(sz) : "memory");
}
__device__ __forceinline__ void sts128(uint32_t addr, uint32_t r0, uint32_t r1, uint32_t r2, uint32_t r3) {
    asm volatile("st.shared.v4.b32 [%0], {%1, %2, %3, %4};" :: "r"(addr), "r"(r0), "r"(r1), "r"(r2), "r"(r3) : "memory");
}
__device__ __forceinline__ uint32_t swz(uint32_t off) { return off ^ ((off >> 3) & 0x70); }

// smem: fp16 slabs [0,30720) | fp32 F buffer [30720,81920) | sMin [81920,+1024)
#define OFF_F   30720
#define OFF_MIN 81920
#define SMEM_BYTES (OFF_MIN + 1024 + 1024)   // 83968

__global__ __launch_bounds__(256, 2)
void conv_mma_kernel(const float* __restrict__ x,
                     const float* __restrict__ bias,
                     float* __restrict__ out) {
    extern __shared__ char smem_raw[];
    uint32_t sb = (smem_u32(smem_raw) + 1023u) & ~1023u;

    const int tid  = threadIdx.x;
    const int wid  = tid >> 5;
    const int lane = tid & 31;
    const int b    = blockIdx.z;
    const int oy0  = blockIdx.y * TROWS;
    const int x0   = blockIdx.x * TPX;

    const int warpM = wid & 1;       // co half: 64*warpM .. +63
    const int warpN = wid >> 1;      // output row pair: rows 2*warpN, 2*warpN+1

    // ---- phase 1: cp.async fp32 tile -> F[row][ci][px20] (zero-filled edges) ----
    // chunks: 10 rows * 64 ci * 5 chunks(16B) = 3200
    const float* xb = x + (size_t)b * CIN * HH * WW;
#pragma unroll 1
    for (int i = 0; i < 13; i++) {
        int c = i * 256 + tid;
        if (c < 3200) {
            int row = c / 320;
            int rem = c - row * 320;
            int ci  = rem / 5;
            int ch  = rem - ci * 5;
            int y   = oy0 + row;
            int ix0 = x0 + ch * 4;
            int szf = (y < HH) ? (WW - ix0) : 0;         // valid floats
            int sz  = min(max(szf, 0) * 4, 16);
            const float* src = (sz > 0) ? xb + ((size_t)ci * HH + y) * WW + ix0
                                        : (const float*)xb;
            uint32_t dst = sb + OFF_F + (uint32_t)(row * 5120 + ci * 80 + ch * 16);
            cp16(dst, src, sz);
        }
    }
    asm volatile("cp.async.commit_group;" ::: "memory");
    asm volatile("cp.async.wait_group 0;" ::: "memory");
    __syncthreads();

    // ---- phase 2: convert F -> fp16 swizzled slabs (conflict-free) ----
    if (tid < INROWS * PXST) {       // 180 columns
        int row = tid / PXST;
        int px  = tid - row * PXST;
        uint32_t fbase = sb + OFF_F + (uint32_t)(row * 5120 + px * 4);
        uint32_t sbase = sb + (uint32_t)(row * SLAB_STRIDE + px * 128);
#pragma unroll
        for (int cig = 0; cig < 8; cig++) {
            uint32_t wv[4];
#pragma unroll
            for (int k = 0; k < 4; k++) {
                float f0, f1;
                asm("ld.shared.f32 %0, [%1];" : "=f"(f0) : "r"(fbase + (uint32_t)((cig * 8 + 2 * k) * 80)));
                asm("ld.shared.f32 %0, [%1];" : "=f"(f1) : "r"(fbase + (uint32_t)((cig * 8 + 2 * k + 1) * 80)));
                __half2 h2 = __floats2half2_rn(f0, f1);
                wv[k] = *(uint32_t*)&h2;
            }
            sts128(sbase + (uint32_t)((cig ^ (px & 7)) << 4), wv[0], wv[1], wv[2], wv[3]);
        }
    }

    // ---- accumulators, init = bias[co] ----
    float acc[4][4][4];
#pragma unroll
    for (int m = 0; m < 4; m++) {
        int r_co = warpM * 64 + m * 16 + (lane >> 2);
        float b0 = __ldg(&bias[r_co]);
        float b1 = __ldg(&bias[r_co + 8]);
#pragma unroll
        for (int f = 0; f < 4; f++) {
            acc[m][f][0] = b0; acc[m][f][1] = b0;
            acc[m][f][2] = b1; acc[m][f][3] = b1;
        }
    }
    __syncthreads();

    const uint4* gw = g_Wfrag;
    const int pxl     = lane & 7;
    const int fhalf   = (lane >> 4) & 1;
    const int kb_lane = ((lane >> 3) & 1) * 16;
    const int awoff   = warpM * 4;

#pragma unroll
    for (int kh = 0; kh < 3; kh++) {
        const uint32_t row0 = sb + (uint32_t)((2 * warpN + kh) * SLAB_STRIDE);
#pragma unroll
        for (int kw = 0; kw < 3; kw++) {
            const int tap = kh * 3 + kw;
#pragma unroll
            for (int ks = 0; ks < 4; ks++) {
                uint4 A[4];
                const int base = (tap * 4 + ks) * 8;
#pragma unroll
                for (int m = 0; m < 4; m++)
                    A[m] = __ldg(&gw[(base + awoff + m) * 32 + lane]);

                uint32_t B[8];
#pragma unroll
                for (int h = 0; h < 2; h++) {
                    uint32_t off = swz((uint32_t)((pxl + fhalf * 8 + kw) * 128 + kb_lane + ks * 32));
                    ldsm4(B[h*4+0], B[h*4+1], B[h*4+2], B[h*4+3],
                          row0 + (uint32_t)(h * SLAB_STRIDE) + off);
                }
#pragma unroll
                for (int m = 0; m < 4; m++) {
#pragma unroll
                    for (int f = 0; f < 4; f++)
                        mma16816(acc[m][f], A[m], B[f*2], B[f*2+1]);
                }
            }
        }
    }

    // ---- epilogue: min over co ----
    float* sMin = (float*)(smem_raw + (sb - smem_u32(smem_raw)) + OFF_MIN);  // [2][128]

#pragma unroll
    for (int f = 0; f < 4; f++) {
        float v0 = __int_as_float(0x7f800000), v1 = v0;
#pragma unroll
        for (int m = 0; m < 4; m++) {
            v0 = fminf(v0, fminf(acc[m][f][0], acc[m][f][2]));
            v1 = fminf(v1, fminf(acc[m][f][1], acc[m][f][3]));
        }
#pragma unroll
        for (int off = 4; off < 32; off <<= 1) {
            v0 = fminf(v0, __shfl_xor_sync(0xffffffffu, v0, off));
            v1 = fminf(v1, __shfl_xor_sync(0xffffffffu, v1, off));
        }
        if ((lane >> 2) == 0) {
            int r_loc = 2 * warpN + (f >> 1);
            int px    = (f & 1) * 8 + (lane & 3) * 2;
            int idx   = r_loc * TPX + px;
            sMin[warpM * 128 + idx]     = v0;
            sMin[warpM * 128 + idx + 1] = v1;
        }
    }
    __syncthreads();

    if (tid < 128) {
        int r = tid >> 4, c = tid & 15;
        int orow = oy0 + r, ocol = x0 + c;
        if (orow < OH && ocol < OW) {
            float m = fminf(sMin[tid], sMin[128 + tid]);
            out[((size_t)b * OH + orow) * OW + ocol] = tanhf(tanhf(m));
        }
    }
}

extern "C" void kernel_launch(void* const* d_in, const int* in_sizes, int n_in,
                              void* d_out, int out_size) {
    const float* x    = (const float*)d_in[0];
    const float* w    = (const float*)d_in[1];
    const float* bias = (const float*)d_in[2];
    float* out = (float*)d_out;

    prep_w<<<(9216 + 255) / 256, 256>>>(w);

    cudaFuncSetAttribute(conv_mma_kernel, cudaFuncAttributeMaxDynamicSharedMemorySize, SMEM_BYTES);
    dim3 grid((OW + TPX - 1) / TPX,      // 14
              (OH + TROWS - 1) / TROWS,  // 28
              16);
    conv_mma_kernel<<<grid, 256, SMEM_BYTES>>>(x, bias, out);
}